// round 1
// baseline (speedup 1.0000x reference)
#include <cuda_runtime.h>
#include <cuda_bf16.h>

#define N_NODES   131072
#define D_MODEL   128
#define NUM_LAYERS 4
#define NODES_PER_EXPR 64
#define NUM_EQ    1024      // 2048 segments / 2

// Ping-pong feature buffers (64MB each) — static device globals (no allocs).
__device__ float g_featA[N_NODES * D_MODEL];
__device__ float g_featB[N_NODES * D_MODEL];

// ---------------------------------------------------------------------------
// Embedding lookup: feats[n][d] = emb[node_idx[n]][d]   (vectorized float4)
// ---------------------------------------------------------------------------
__global__ void embed_kernel(const int* __restrict__ node_idx,
                             const float* __restrict__ emb) {
    int i = blockIdx.x * blockDim.x + threadIdx.x;   // over N_NODES*32 float4s
    if (i >= N_NODES * (D_MODEL / 4)) return;
    int n  = i >> 5;          // node
    int d4 = i & 31;          // float4 within row
    const float4* e4 = reinterpret_cast<const float4*>(emb);
    float4* o4 = reinterpret_cast<float4*>(g_featA);
    o4[i] = e4[node_idx[n] * (D_MODEL / 4) + d4];
}

// ---------------------------------------------------------------------------
// Fused layer: H = relu(gather(feats) @ W0 + b0); out = H @ W1 + b1
// Block: 64 nodes x 128 outputs, 256 threads (16x16), 4x8 microtile/thread.
// ---------------------------------------------------------------------------
__global__ __launch_bounds__(256, 3)
void layer_kernel(int pingpong,                 // 0: A->B, 1: B->A
                  const int*   __restrict__ neighbors,
                  const float* __restrict__ W0l,
                  const float* __restrict__ b0l,
                  const float* __restrict__ W1l,
                  const float* __restrict__ b1l) {
    const float* fin  = pingpong ? g_featB : g_featA;
    float*       fout = pingpong ? g_featA : g_featB;

    __shared__ float sH[64 * 129];       // H tile, padded stride 129 (33024 B)
    __shared__ float sB[16 * 128];       // B tile (W0/W1 chunk)      (8192 B)
    __shared__ float sA[16 * 65];        // A tile transposed [kk][row] (4160 B)
    __shared__ int   sNbr[64 * 4];       // neighbor ids for this block (1024 B)

    const int tid = threadIdx.x;
    const int tx = tid & 15;             // output-column group
    const int ty = tid >> 4;             // output-row group
    const int base = blockIdx.x * 64;    // first node of tile

    // cache neighbor indices
    sNbr[tid] = neighbors[base * 4 + tid];           // 256 == 64*4 exactly
    __syncthreads();

    const int rowLoad = tid >> 2;        // 0..63 (A-load row)
    const int seg     = tid & 3;         // 0..3  (A-load float4 slot)

    float acc[4][8];
    #pragma unroll
    for (int i = 0; i < 4; i++)
        #pragma unroll
        for (int j = 0; j < 8; j++) acc[i][j] = 0.f;

    const float4* fin4 = reinterpret_cast<const float4*>(fin);
    const float4* W04  = reinterpret_cast<const float4*>(W0l);

    // -------- Phase 1: gathered[64x512] @ W0[512x128] --------
    #pragma unroll 1
    for (int j = 0; j < 4; j++) {                    // neighbor slot
        const int src = sNbr[rowLoad * 4 + j];
        const bool pad = (src == N_NODES);
        const int srcBase = pad ? 0 : src * (D_MODEL / 4);   // float4 row base

        #pragma unroll 1
        for (int c0 = 0; c0 < D_MODEL; c0 += 16) {   // K-chunk within neighbor
            // A tile: 64 rows x 16 k  (one float4 per thread)
            float4 av = make_float4(0.f, 0.f, 0.f, 0.f);
            if (!pad) av = fin4[srcBase + (c0 >> 2) + seg];
            sA[(seg * 4 + 0) * 65 + rowLoad] = av.x;
            sA[(seg * 4 + 1) * 65 + rowLoad] = av.y;
            sA[(seg * 4 + 2) * 65 + rowLoad] = av.z;
            sA[(seg * 4 + 3) * 65 + rowLoad] = av.w;

            // B tile: W0 rows [j*128+c0 .. +16), all 128 cols (2 float4/thread)
            const int krow = j * D_MODEL + c0;       // global K row of chunk
            float4* sB4 = reinterpret_cast<float4*>(sB);
            #pragma unroll
            for (int p = 0; p < 2; p++)
                sB4[tid * 2 + p] = W04[krow * (D_MODEL / 4) + tid * 2 + p];
            __syncthreads();

            #pragma unroll
            for (int kk = 0; kk < 16; kk++) {
                float a[4], b[8];
                #pragma unroll
                for (int i = 0; i < 4; i++) a[i] = sA[kk * 65 + ty * 4 + i];
                #pragma unroll
                for (int jj = 0; jj < 8; jj++) b[jj] = sB[kk * 128 + tx + 16 * jj];
                #pragma unroll
                for (int i = 0; i < 4; i++)
                    #pragma unroll
                    for (int jj = 0; jj < 8; jj++)
                        acc[i][jj] = fmaf(a[i], b[jj], acc[i][jj]);
            }
            __syncthreads();
        }
    }

    // bias + relu -> H smem
    #pragma unroll
    for (int jj = 0; jj < 8; jj++) {
        const int col = tx + 16 * jj;
        const float bb = b0l[col];
        #pragma unroll
        for (int i = 0; i < 4; i++) {
            float h = acc[i][jj] + bb;
            sH[(ty * 4 + i) * 129 + col] = h > 0.f ? h : 0.f;
        }
    }
    __syncthreads();

    // -------- Phase 2: H[64x128] @ W1[128x128] --------
    float acc2[4][8];
    #pragma unroll
    for (int i = 0; i < 4; i++)
        #pragma unroll
        for (int j = 0; j < 8; j++) acc2[i][j] = 0.f;

    const float4* W14 = reinterpret_cast<const float4*>(W1l);
    #pragma unroll 1
    for (int c0 = 0; c0 < D_MODEL; c0 += 16) {
        float4* sB4 = reinterpret_cast<float4*>(sB);
        #pragma unroll
        for (int p = 0; p < 2; p++)
            sB4[tid * 2 + p] = W14[c0 * (D_MODEL / 4) + tid * 2 + p];
        __syncthreads();

        #pragma unroll
        for (int kk = 0; kk < 16; kk++) {
            float a[4], b[8];
            #pragma unroll
            for (int i = 0; i < 4; i++) a[i] = sH[(ty * 4 + i) * 129 + c0 + kk];
            #pragma unroll
            for (int jj = 0; jj < 8; jj++) b[jj] = sB[kk * 128 + tx + 16 * jj];
            #pragma unroll
            for (int i = 0; i < 4; i++)
                #pragma unroll
                for (int jj = 0; jj < 8; jj++)
                    acc2[i][jj] = fmaf(a[i], b[jj], acc2[i][jj]);
        }
        __syncthreads();
    }

    // bias + store
    #pragma unroll
    for (int jj = 0; jj < 8; jj++) {
        const int col = tx + 16 * jj;
        const float bb = b1l[col];
        #pragma unroll
        for (int i = 0; i < 4; i++)
            fout[(base + ty * 4 + i) * D_MODEL + col] = acc2[i][jj] + bb;
    }
}

// ---------------------------------------------------------------------------
// Readout: per equation b, logits[b] = dot(meanL, meanR) + out_bias
//   = sum_d (sumL_d * sumR_d) / 4096 + out_bias
// feats in g_featA (after 4 layers: A->B->A->B->A).
// ---------------------------------------------------------------------------
__global__ void readout_kernel(const float* __restrict__ out_bias,
                               float* __restrict__ logits) {
    const int b = blockIdx.x;        // 0..1023
    const int t = threadIdx.x;       // 0..127 (feature dim)
    const float* L = g_featA + (size_t)(2 * b) * NODES_PER_EXPR * D_MODEL;
    const float* R = L + NODES_PER_EXPR * D_MODEL;

    float sl = 0.f, sr = 0.f;
    #pragma unroll 8
    for (int i = 0; i < NODES_PER_EXPR; i++) {
        sl += L[i * D_MODEL + t];
        sr += R[i * D_MODEL + t];
    }
    float v = sl * sr;

    // block reduce over 128 threads
    #pragma unroll
    for (int o = 16; o > 0; o >>= 1) v += __shfl_down_sync(0xffffffffu, v, o);
    __shared__ float red[4];
    if ((t & 31) == 0) red[t >> 5] = v;
    __syncthreads();
    if (t == 0)
        logits[b] = (red[0] + red[1] + red[2] + red[3]) * (1.f / 4096.f)
                    + out_bias[0];
}

// ---------------------------------------------------------------------------
extern "C" void kernel_launch(void* const* d_in, const int* in_sizes, int n_in,
                              void* d_out, int out_size) {
    const int*   node_idx = (const int*)  d_in[0];
    const int*   neighbors= (const int*)  d_in[1];
    // d_in[2] = seg_ids (contiguous arange/64 by construction; unused)
    const float* emb      = (const float*)d_in[3];
    const float* W0       = (const float*)d_in[4];
    const float* b0       = (const float*)d_in[5];
    const float* W1       = (const float*)d_in[6];
    const float* b1       = (const float*)d_in[7];
    const float* out_bias = (const float*)d_in[8];
    float* logits = (float*)d_out;

    // Embedding
    {
        int total = N_NODES * (D_MODEL / 4);
        embed_kernel<<<(total + 255) / 256, 256>>>(node_idx, emb);
    }

    // 4 fused layers, ping-pong A->B->A->B->A
    for (int l = 0; l < NUM_LAYERS; l++) {
        layer_kernel<<<N_NODES / 64, 256>>>(
            l & 1, neighbors,
            W0 + (size_t)l * 4 * D_MODEL * D_MODEL,
            b0 + (size_t)l * D_MODEL,
            W1 + (size_t)l * D_MODEL * D_MODEL,
            b1 + (size_t)l * D_MODEL);
    }

    // Readout
    readout_kernel<<<NUM_EQ, D_MODEL>>>(out_bias, logits);
}

// round 3
// speedup vs baseline: 3.1129x; 3.1129x over previous
#include <cuda_runtime.h>
#include <cuda_bf16.h>
#include <cstdint>

#define N_NODES   131072
#define D_MODEL   128
#define NUM_LAYERS 4
#define NUM_EQ    1024
#define NUM_TILES (N_NODES / 128)   // 1024 CTAs per layer

// smem: [0..2048) neighbor ids, [4096..69632) buf0, [69632..135168) buf1
// buf layout: A_hi 16K | A_lo 16K | B_hi 16K | B_lo 16K
#define SMEM_BYTES (4096 + 2 * 65536)

// ---------------- static device buffers (no allocs allowed) ----------------
__device__ __align__(16) __nv_bfloat16 g_hi0[N_NODES * D_MODEL];
__device__ __align__(16) __nv_bfloat16 g_lo0[N_NODES * D_MODEL];
__device__ __align__(16) __nv_bfloat16 g_hi1[N_NODES * D_MODEL];
__device__ __align__(16) __nv_bfloat16 g_lo1[N_NODES * D_MODEL];
// weight blobs: [layer][sub 0..9][hi/lo][128 n-rows x 64 k bf16, ldsm-swizzled]
// sub 0..7 -> W0 K-chunks (K=512), sub 8..9 -> W1 K-chunks (K=128)
__device__ __align__(16) __nv_bfloat16 g_wblob[NUM_LAYERS * 10 * 2 * 8192];

// ---------------- helpers ----------------
__device__ __forceinline__ uint32_t smem_u32(const void* p) {
    uint32_t a;
    asm("{ .reg .u64 t; cvta.to.shared.u64 t, %1; cvt.u32.u64 %0, t; }"
        : "=r"(a) : "l"(p));
    return a;
}
#define CP16(dst, src, sz) \
    asm volatile("cp.async.cg.shared.global [%0], [%1], 16, %2;" \
                 :: "r"(dst), "l"(src), "r"(sz) : "memory")
#define CPCOMMIT() asm volatile("cp.async.commit_group;" ::: "memory")
#define CPWAIT(N)  asm volatile("cp.async.wait_group " #N ";" ::: "memory")

__device__ __forceinline__ void ldsm4(uint32_t* r, uint32_t addr) {
    asm volatile("ldmatrix.sync.aligned.m8n8.x4.shared.b16 {%0,%1,%2,%3}, [%4];"
                 : "=r"(r[0]), "=r"(r[1]), "=r"(r[2]), "=r"(r[3]) : "r"(addr));
}
__device__ __forceinline__ void hmma(float* d, const uint32_t* a,
                                     uint32_t b0, uint32_t b1) {
    asm volatile(
        "mma.sync.aligned.m16n8k16.row.col.f32.bf16.bf16.f32 "
        "{%0,%1,%2,%3}, {%4,%5,%6,%7}, {%8,%9}, {%0,%1,%2,%3};"
        : "+f"(d[0]), "+f"(d[1]), "+f"(d[2]), "+f"(d[3])
        : "r"(a[0]), "r"(a[1]), "r"(a[2]), "r"(a[3]), "r"(b0), "r"(b1));
}
// tile: 128 rows x 64 k bf16 (128B rows, 8x16B chunks), XOR swizzle for ldsm
__device__ __forceinline__ uint32_t tadr(uint32_t base, int row, int ck) {
    return base + row * 128 + (((uint32_t)ck ^ (row & 7)) << 4);
}
__device__ __forceinline__ void split2(float x0, float x1, uint32_t& hi, uint32_t& lo) {
    __nv_bfloat16 h0 = __float2bfloat16_rn(x0);
    __nv_bfloat16 h1 = __float2bfloat16_rn(x1);
    float l0 = x0 - __bfloat162float(h0);
    float l1 = x1 - __bfloat162float(h1);
    __nv_bfloat162 hh = __halves2bfloat162(h0, h1);
    __nv_bfloat162 ll = __floats2bfloat162_rn(l0, l1);
    hi = *reinterpret_cast<uint32_t*>(&hh);
    lo = *reinterpret_cast<uint32_t*>(&ll);
}

// ---------------------------------------------------------------------------
// prep: transposed, hi/lo-split, ldsm-swizzled weight blobs
// ---------------------------------------------------------------------------
__global__ void prep_w(const float* __restrict__ W0, const float* __restrict__ W1) {
    int i = blockIdx.x * blockDim.x + threadIdx.x;
    if (i >= NUM_LAYERS * 10 * 2 * 8192) return;
    int e   = i & 8191;           // element within blob
    int g   = i >> 14;            // l*10 + sub
    int v   = (i >> 13) & 1;      // hi/lo
    int sub = g % 10;
    int l   = g / 10;
    int n   = e >> 6;             // N row 0..127
    int kk  = e & 63;             // K within subtile
    float w;
    if (sub < 8) w = W0[((size_t)l * 512 + sub * 64 + kk) * 128 + n];
    else         w = W1[((size_t)l * 128 + (sub - 8) * 64 + kk) * 128 + n];
    __nv_bfloat16 h = __float2bfloat16_rn(w);
    __nv_bfloat16 out = (v == 0) ? h : __float2bfloat16_rn(w - __bfloat162float(h));
    int ck = kk >> 3;
    uint32_t sw = (uint32_t)(n * 128) + (((uint32_t)ck ^ (n & 7)) << 4) + (kk & 7) * 2;
    *reinterpret_cast<__nv_bfloat16*>(
        reinterpret_cast<char*>(g_wblob) + (size_t)(i - e) * 2 + sw) = out;
}

// ---------------------------------------------------------------------------
// embed: feats = emb[node_idx], split to bf16 hi/lo into buffer 0
// ---------------------------------------------------------------------------
__global__ void embed_k(const int* __restrict__ node_idx, const float* __restrict__ emb) {
    int i = blockIdx.x * blockDim.x + threadIdx.x;
    if (i >= N_NODES * (D_MODEL / 4)) return;
    int n  = i >> 5;
    int c4 = i & 31;
    float4 vv = reinterpret_cast<const float4*>(emb)[node_idx[n] * 32 + c4];
    uint32_t h01, l01, h23, l23;
    split2(vv.x, vv.y, h01, l01);
    split2(vv.z, vv.w, h23, l23);
    reinterpret_cast<uint2*>(g_hi0)[i] = make_uint2(h01, h23);
    reinterpret_cast<uint2*>(g_lo0)[i] = make_uint2(l01, l23);
}

// ---------------------------------------------------------------------------
// fused layer: HMMA bf16 hi/lo 3-term split, cp.async double-buffered
// ---------------------------------------------------------------------------
__device__ __forceinline__ void compute64(float acc[2][8][4], uint32_t bufA,
                                          uint32_t bufB, int lane, int wy, int wx) {
    #pragma unroll
    for (int ks = 0; ks < 4; ks++) {
        const int rsel = lane & 15;
        const int csel = 2 * ks + (lane >> 4);
        uint32_t ah[2][4], al[2][4];
        #pragma unroll
        for (int mi = 0; mi < 2; mi++) {
            int row = wy * 32 + mi * 16 + rsel;
            ldsm4(ah[mi], tadr(bufA,         row, csel));
            ldsm4(al[mi], tadr(bufA + 16384, row, csel));
        }
        #pragma unroll
        for (int g = 0; g < 4; g++) {
            int row = wx * 64 + g * 16 + rsel;
            uint32_t bh[4], bl[4];
            ldsm4(bh, tadr(bufB,         row, csel));
            ldsm4(bl, tadr(bufB + 16384, row, csel));
            #pragma unroll
            for (int mi = 0; mi < 2; mi++) {
                hmma(acc[mi][2 * g],     ah[mi], bh[0], bh[2]);
                hmma(acc[mi][2 * g],     ah[mi], bl[0], bl[2]);
                hmma(acc[mi][2 * g],     al[mi], bh[0], bh[2]);
                hmma(acc[mi][2 * g + 1], ah[mi], bh[1], bh[3]);
                hmma(acc[mi][2 * g + 1], ah[mi], bl[1], bl[3]);
                hmma(acc[mi][2 * g + 1], al[mi], bh[1], bh[3]);
            }
        }
    }
}

__global__ __launch_bounds__(256)
void layer_k(int l, int srcBuf, const int* __restrict__ neighbors,
             const float* __restrict__ b0, const float* __restrict__ b1) {
    extern __shared__ __align__(16) char smem[];
    int* sNbr = (int*)smem;
    const uint32_t sb = smem_u32(smem);
    const uint32_t BUF0 = sb + 4096, BUF1 = BUF0 + 65536;

    const int tid = threadIdx.x, lane = tid & 31, wid = tid >> 5;
    const int wy = wid >> 1, wx = wid & 1;

    const __nv_bfloat16* fh = srcBuf ? g_hi1 : g_hi0;
    const __nv_bfloat16* fl = srcBuf ? g_lo1 : g_lo0;
    __nv_bfloat16* oh = srcBuf ? g_hi0 : g_hi1;
    __nv_bfloat16* ol = srcBuf ? g_lo0 : g_lo1;

    sNbr[tid]       = neighbors[blockIdx.x * 512 + tid];
    sNbr[tid + 256] = neighbors[blockIdx.x * 512 + 256 + tid];
    __syncthreads();

    const char* fhB = reinterpret_cast<const char*>(fh);
    const char* flB = reinterpret_cast<const char*>(fl);
    const char* blobB = reinterpret_cast<const char*>(g_wblob);

    // issue one K=64 stage: A gather (zfill for pad node) + B blob copy
    auto issue = [&](int s) {
        const uint32_t buf = (s & 1) ? BUF1 : BUF0;
        const int j = s >> 1, half = s & 1;
        const size_t blobOff = (size_t)(l * 10 + s) * 32768;
        #pragma unroll
        for (int r = 0; r < 4; r++) {
            int c = tid + 256 * r;                 // 0..1023
            int row = c >> 3, ck = c & 7;
            int sn = sNbr[row * 4 + j];
            uint32_t sz = (sn == N_NODES) ? 0u : 16u;
            size_t so = (size_t)sn * 256 + half * 128 + ck * 16;
            uint32_t dA = tadr(buf, row, ck);
            CP16(dA,         fhB + so, sz);
            CP16(dA + 16384, flB + so, sz);
            // B: pre-swizzled blobs, linear copy
            CP16(buf + 32768 + c * 16, blobB + blobOff + c * 16, 16u);
            CP16(buf + 49152 + c * 16, blobB + blobOff + 16384 + c * 16, 16u);
        }
    };

    float acc[2][8][4];
    #pragma unroll
    for (int mi = 0; mi < 2; mi++)
        #pragma unroll
        for (int ni = 0; ni < 8; ni++)
            #pragma unroll
            for (int q = 0; q < 4; q++) acc[mi][ni][q] = 0.f;

    // -------- GEMM1: gathered[128x512] @ W0, 8 stages --------
    issue(0); CPCOMMIT();
    #pragma unroll 1
    for (int s = 0; s < 8; s++) {
        if (s < 7) { issue(s + 1); CPCOMMIT(); CPWAIT(1); }
        else       { CPWAIT(0); }
        __syncthreads();
        const uint32_t buf = (s & 1) ? BUF1 : BUF0;
        compute64(acc, buf, buf + 32768, lane, wy, wx);
        __syncthreads();
    }

    // -------- epilogue1: W1 copies + H = relu(acc+b0) -> hi/lo into A tiles ----
    #pragma unroll
    for (int r = 0; r < 16; r++) {
        int idx = tid + 256 * r;                   // 0..4095
        int region = idx >> 10;                    // 0:b0H 1:b0L 2:b1H 3:b1L
        int c = idx & 1023;
        uint32_t dst = ((region < 2) ? BUF0 : BUF1) + 32768 +
                       ((region & 1) << 14) + c * 16;
        size_t src = (size_t)(l * 10 + 8 + (region >> 1)) * 32768 +
                     (size_t)(region & 1) * 16384 + (size_t)c * 16;
        CP16(dst, blobB + src, 16u);
    }
    CPCOMMIT();

    const uint32_t hbuf = wx ? BUF1 : BUF0;        // wx=0 -> k 0..63, wx=1 -> 64..127
    #pragma unroll
    for (int mi = 0; mi < 2; mi++) {
        #pragma unroll
        for (int ni = 0; ni < 8; ni++) {
            int kl = ni * 8 + (lane & 3) * 2;      // k within GEMM2 subtile
            int ncol = wx * 64 + kl;               // GEMM1 output column
            float bb0 = __ldg(&b0[ncol]), bb1 = __ldg(&b0[ncol + 1]);
            #pragma unroll
            for (int h = 0; h < 2; h++) {          // row halves
                int row = wy * 32 + mi * 16 + (lane >> 2) + h * 8;
                float x0 = acc[mi][ni][2 * h]     + bb0;
                float x1 = acc[mi][ni][2 * h + 1] + bb1;
                x0 = x0 > 0.f ? x0 : 0.f;
                x1 = x1 > 0.f ? x1 : 0.f;
                uint32_t hi2, lo2;
                split2(x0, x1, hi2, lo2);
                uint32_t a = tadr(hbuf, row, kl >> 3) + (kl & 7) * 2;
                asm volatile("st.shared.b32 [%0], %1;" :: "r"(a), "r"(hi2) : "memory");
                asm volatile("st.shared.b32 [%0], %1;" :: "r"(a + 16384), "r"(lo2) : "memory");
            }
        }
    }
    CPWAIT(0);
    __syncthreads();

    // -------- GEMM2: H[128x128] @ W1, 2 stages --------
    #pragma unroll
    for (int mi = 0; mi < 2; mi++)
        #pragma unroll
        for (int ni = 0; ni < 8; ni++)
            #pragma unroll
            for (int q = 0; q < 4; q++) acc[mi][ni][q] = 0.f;
    compute64(acc, BUF0, BUF0 + 32768, lane, wy, wx);
    compute64(acc, BUF1, BUF1 + 32768, lane, wy, wx);

    // -------- epilogue2: out = acc + b1 -> hi/lo bf16 to global --------
    #pragma unroll
    for (int mi = 0; mi < 2; mi++) {
        #pragma unroll
        for (int ni = 0; ni < 8; ni++) {
            int ncol = wx * 64 + ni * 8 + (lane & 3) * 2;
            float bb0 = __ldg(&b1[ncol]), bb1 = __ldg(&b1[ncol + 1]);
            #pragma unroll
            for (int h = 0; h < 2; h++) {
                int row = wy * 32 + mi * 16 + (lane >> 2) + h * 8;
                size_t gOff = (size_t)(blockIdx.x * 128 + row) * 128 + ncol;
                float x0 = acc[mi][ni][2 * h]     + bb0;
                float x1 = acc[mi][ni][2 * h + 1] + bb1;
                uint32_t hi2, lo2;
                split2(x0, x1, hi2, lo2);
                *reinterpret_cast<uint32_t*>(oh + gOff) = hi2;
                *reinterpret_cast<uint32_t*>(ol + gOff) = lo2;
            }
        }
    }
}

// ---------------------------------------------------------------------------
// readout: logits[b] = dot(meanL, meanR) + out_bias   (feats = hi0 + lo0)
// ---------------------------------------------------------------------------
__global__ void readout_k(const float* __restrict__ out_bias, float* __restrict__ logits) {
    const int b = blockIdx.x;
    const int t = threadIdx.x;   // 0..127
    size_t baseL = (size_t)(2 * b) * 64 * 128;
    size_t baseR = baseL + 64 * 128;
    float sl = 0.f, sr = 0.f;
    #pragma unroll 8
    for (int i = 0; i < 64; i++) {
        sl += __bfloat162float(g_hi0[baseL + i * 128 + t]) +
              __bfloat162float(g_lo0[baseL + i * 128 + t]);
        sr += __bfloat162float(g_hi0[baseR + i * 128 + t]) +
              __bfloat162float(g_lo0[baseR + i * 128 + t]);
    }
    float v = sl * sr;
    #pragma unroll
    for (int o = 16; o > 0; o >>= 1) v += __shfl_down_sync(0xffffffffu, v, o);
    __shared__ float red[4];
    if ((t & 31) == 0) red[t >> 5] = v;
    __syncthreads();
    if (t == 0)
        logits[b] = (red[0] + red[1] + red[2] + red[3]) * (1.f / 4096.f) + out_bias[0];
}

// ---------------------------------------------------------------------------
extern "C" void kernel_launch(void* const* d_in, const int* in_sizes, int n_in,
                              void* d_out, int out_size) {
    const int*   node_idx  = (const int*)  d_in[0];
    const int*   neighbors = (const int*)  d_in[1];
    const float* emb       = (const float*)d_in[3];
    const float* W0        = (const float*)d_in[4];
    const float* b0        = (const float*)d_in[5];
    const float* W1        = (const float*)d_in[6];
    const float* b1        = (const float*)d_in[7];
    const float* out_bias  = (const float*)d_in[8];
    float* logits = (float*)d_out;

    cudaFuncSetAttribute(layer_k, cudaFuncAttributeMaxDynamicSharedMemorySize, SMEM_BYTES);

    {
        int total = NUM_LAYERS * 10 * 2 * 8192;
        prep_w<<<(total + 255) / 256, 256>>>(W0, W1);
    }
    {
        int total = N_NODES * (D_MODEL / 4);
        embed_k<<<(total + 255) / 256, 256>>>(node_idx, emb);
    }
    for (int l = 0; l < NUM_LAYERS; l++) {
        layer_k<<<NUM_TILES, 256, SMEM_BYTES>>>(
            l, l & 1, neighbors,
            b0 + (size_t)l * D_MODEL,
            b1 + (size_t)l * D_MODEL);
    }
    readout_k<<<NUM_EQ, D_MODEL>>>(out_bias, logits);
}

// round 4
// speedup vs baseline: 5.4884x; 1.7631x over previous
#include <cuda_runtime.h>
#include <cuda_fp16.h>
#include <cstdint>

#define N_NODES   131072
#define NUM_LAYERS 4
#define NUM_EQ    1024
#define NUM_TILES 1024
#define SCALE 64.0f

// smem: [0..2048) neighbor ids, [4096..53248) buf0, [53248..102400) buf1
// buf layout (49152 B): A 16K | B_hi 16K | B_lo 16K
#define SMEM_BYTES (4096 + 2 * 49152)

// ---------------- static device buffers (no allocs allowed) ----------------
__device__ __align__(16) __half g_f0[N_NODES * 128];
__device__ __align__(16) __half g_f1[N_NODES * 128];
// weight blobs: [layer][sub 0..9][hi/lo][128 n-rows x 64 k fp16, ldsm-swizzled]
// sub 0..7 -> W0 K-chunks (K=512), sub 8..9 -> W1 K-chunks (K=128)
__device__ __align__(16) __half g_wblob[NUM_LAYERS * 10 * 2 * 8192];

// ---------------- helpers ----------------
__device__ __forceinline__ uint32_t smem_u32(const void* p) {
    uint32_t a;
    asm("{ .reg .u64 t; cvta.to.shared.u64 t, %1; cvt.u32.u64 %0, t; }"
        : "=r"(a) : "l"(p));
    return a;
}
#define CP16(dst, src, sz) \
    asm volatile("cp.async.cg.shared.global [%0], [%1], 16, %2;" \
                 :: "r"(dst), "l"(src), "r"(sz) : "memory")
#define CPCOMMIT() asm volatile("cp.async.commit_group;" ::: "memory")
#define CPWAIT(N)  asm volatile("cp.async.wait_group " #N ";" ::: "memory")

__device__ __forceinline__ void ldsm4(uint32_t* r, uint32_t addr) {
    asm volatile("ldmatrix.sync.aligned.m8n8.x4.shared.b16 {%0,%1,%2,%3}, [%4];"
                 : "=r"(r[0]), "=r"(r[1]), "=r"(r[2]), "=r"(r[3]) : "r"(addr));
}
__device__ __forceinline__ void hmma(float* d, const uint32_t* a,
                                     uint32_t b0, uint32_t b1) {
    asm volatile(
        "mma.sync.aligned.m16n8k16.row.col.f32.f16.f16.f32 "
        "{%0,%1,%2,%3}, {%4,%5,%6,%7}, {%8,%9}, {%0,%1,%2,%3};"
        : "+f"(d[0]), "+f"(d[1]), "+f"(d[2]), "+f"(d[3])
        : "r"(a[0]), "r"(a[1]), "r"(a[2]), "r"(a[3]), "r"(b0), "r"(b1));
}
// tile: 128 rows x 64 k fp16 (128B rows, 8x16B chunks), XOR swizzle for ldsm
__device__ __forceinline__ uint32_t tadr(uint32_t base, int row, int ck) {
    return base + row * 128 + (((uint32_t)ck ^ (row & 7)) << 4);
}

// ---------------------------------------------------------------------------
// prep: transposed, fp16 hi/lo-split, ldsm-swizzled weight blobs
// ---------------------------------------------------------------------------
__global__ void prep_w(const float* __restrict__ W0, const float* __restrict__ W1) {
    int i = blockIdx.x * blockDim.x + threadIdx.x;
    if (i >= NUM_LAYERS * 10 * 2 * 8192) return;
    int e   = i & 8191;           // element within 8192-elem blob
    int v   = (i >> 13) & 1;      // hi/lo
    int g   = i >> 14;            // l*10 + sub
    int sub = g % 10;
    int l   = g / 10;
    int n   = e >> 6;             // N row 0..127
    int kk  = e & 63;             // K within subtile
    float w;
    if (sub < 8) w = W0[((size_t)l * 512 + sub * 64 + kk) * 128 + n];
    else         w = W1[((size_t)l * 128 + (sub - 8) * 64 + kk) * 128 + n];
    __half h = __float2half_rn(w);
    __half out = (v == 0) ? h : __float2half_rn(w - __half2float(h));
    int ck = kk >> 3;
    uint32_t sw = (uint32_t)(n * 128) + (((uint32_t)ck ^ (n & 7)) << 4) + (kk & 7) * 2;
    *reinterpret_cast<__half*>(
        reinterpret_cast<char*>(g_wblob) + (size_t)(i - e) * 2 + sw) = out;
}

// ---------------------------------------------------------------------------
// embed: feats = SCALE * emb[node_idx]  -> fp16 into buffer 0
// ---------------------------------------------------------------------------
__global__ void embed_k(const int* __restrict__ node_idx, const float* __restrict__ emb) {
    int i = blockIdx.x * blockDim.x + threadIdx.x;   // one per 4 elems
    if (i >= N_NODES * 32) return;
    int n  = i >> 5;
    int c4 = i & 31;
    float4 vv = reinterpret_cast<const float4*>(emb)[node_idx[n] * 32 + c4];
    __half2 p0 = __floats2half2_rn(vv.x * SCALE, vv.y * SCALE);
    __half2 p1 = __floats2half2_rn(vv.z * SCALE, vv.w * SCALE);
    reinterpret_cast<uint2*>(g_f0)[i] =
        make_uint2(*reinterpret_cast<uint32_t*>(&p0), *reinterpret_cast<uint32_t*>(&p1));
}

// ---------------------------------------------------------------------------
// fused layer: fp16 HMMA, A single / B hi+lo (2-term), double-buffered
// ---------------------------------------------------------------------------
__device__ __forceinline__ void compute64(float acc[2][8][4], uint32_t buf,
                                          int lane, int wy, int wx) {
    #pragma unroll
    for (int ks = 0; ks < 4; ks++) {
        const int rsel = lane & 15;
        const int csel = 2 * ks + (lane >> 4);
        uint32_t a[2][4];
        #pragma unroll
        for (int mi = 0; mi < 2; mi++)
            ldsm4(a[mi], tadr(buf, wy * 32 + mi * 16 + rsel, csel));
        #pragma unroll
        for (int g = 0; g < 4; g++) {
            int row = wx * 64 + g * 16 + rsel;
            uint32_t bh[4], bl[4];
            ldsm4(bh, tadr(buf + 16384, row, csel));
            ldsm4(bl, tadr(buf + 32768, row, csel));
            #pragma unroll
            for (int mi = 0; mi < 2; mi++) {
                hmma(acc[mi][2 * g],     a[mi], bh[0], bh[2]);
                hmma(acc[mi][2 * g],     a[mi], bl[0], bl[2]);
                hmma(acc[mi][2 * g + 1], a[mi], bh[1], bh[3]);
                hmma(acc[mi][2 * g + 1], a[mi], bl[1], bl[3]);
            }
        }
    }
}

__global__ __launch_bounds__(256, 2)
void layer_k(int l, int srcBuf, const int* __restrict__ neighbors,
             const float* __restrict__ b0, const float* __restrict__ b1) {
    extern __shared__ __align__(16) char smem[];
    int* sNbr = (int*)smem;
    const uint32_t sb = smem_u32(smem);
    const uint32_t BUF0 = sb + 4096, BUF1 = BUF0 + 49152;

    const int tid = threadIdx.x, lane = tid & 31, wid = tid >> 5;
    const int wy = wid >> 1, wx = wid & 1;

    const __half* fin = srcBuf ? g_f1 : g_f0;
    __half* fout      = srcBuf ? g_f0 : g_f1;

    sNbr[tid]       = neighbors[blockIdx.x * 512 + tid];
    sNbr[tid + 256] = neighbors[blockIdx.x * 512 + 256 + tid];
    __syncthreads();

    const char* finB  = reinterpret_cast<const char*>(fin);
    const char* blobB = reinterpret_cast<const char*>(g_wblob);

    // one K=64 stage: A gather (zfill for pad node) + B hi/lo blob copy
    auto issue = [&](int s) {
        const uint32_t buf = (s & 1) ? BUF1 : BUF0;
        const int j = s >> 1, half = s & 1;
        const size_t blobOff = (size_t)(l * 10 + s) * 32768;
        #pragma unroll
        for (int r = 0; r < 4; r++) {
            int c = tid + 256 * r;                 // 0..1023
            int row = c >> 3, ck = c & 7;
            int sn = sNbr[row * 4 + j];
            uint32_t sz = (sn == N_NODES) ? 0u : 16u;
            size_t so = (size_t)sn * 256 + half * 128 + ck * 16;
            CP16(tadr(buf, row, ck), finB + so, sz);
            // B: pre-swizzled blobs, linear copies
            CP16(buf + 16384 + c * 16, blobB + blobOff + c * 16, 16u);
            CP16(buf + 32768 + c * 16, blobB + blobOff + 16384 + c * 16, 16u);
        }
    };

    float acc[2][8][4];
    #pragma unroll
    for (int mi = 0; mi < 2; mi++)
        #pragma unroll
        for (int ni = 0; ni < 8; ni++)
            #pragma unroll
            for (int q = 0; q < 4; q++) acc[mi][ni][q] = 0.f;

    // -------- GEMM1: gathered[128x512] @ W0, 8 K=64 stages --------
    issue(0); CPCOMMIT();
    #pragma unroll 1
    for (int s = 0; s < 8; s++) {
        if (s < 7) { issue(s + 1); CPCOMMIT(); CPWAIT(1); }
        else       { CPWAIT(0); }
        __syncthreads();
        compute64(acc, (s & 1) ? BUF1 : BUF0, lane, wy, wx);
        __syncthreads();
    }

    // -------- epilogue1: W1 copies + H = relu(acc + s*b0) -> fp16 A tiles ----
    #pragma unroll
    for (int r = 0; r < 16; r++) {
        int idx = tid + 256 * r;                   // 0..4095
        int region = idx >> 10;                    // 0:s8H 1:s8L 2:s9H 3:s9L
        int c = idx & 1023;
        uint32_t dst = ((region < 2) ? BUF0 : BUF1) + 16384 +
                       ((region & 1) << 14) + c * 16;
        size_t src = (size_t)(l * 10 + 8 + (region >> 1)) * 32768 +
                     (size_t)(region & 1) * 16384 + (size_t)c * 16;
        CP16(dst, blobB + src, 16u);
    }
    CPCOMMIT();

    const uint32_t hbuf = wx ? BUF1 : BUF0;        // wx=0 -> k 0..63, wx=1 -> 64..127
    #pragma unroll
    for (int mi = 0; mi < 2; mi++) {
        #pragma unroll
        for (int ni = 0; ni < 8; ni++) {
            int kl = ni * 8 + (lane & 3) * 2;      // k within GEMM2 subtile
            int ncol = wx * 64 + kl;               // GEMM1 output column
            float bb0 = __ldg(&b0[ncol]) * SCALE;
            float bb1 = __ldg(&b0[ncol + 1]) * SCALE;
            #pragma unroll
            for (int h = 0; h < 2; h++) {          // row halves
                int row = wy * 32 + mi * 16 + (lane >> 2) + h * 8;
                float x0 = acc[mi][ni][2 * h]     + bb0;
                float x1 = acc[mi][ni][2 * h + 1] + bb1;
                x0 = x0 > 0.f ? x0 : 0.f;
                x1 = x1 > 0.f ? x1 : 0.f;
                __half2 p = __floats2half2_rn(x0, x1);
                uint32_t a = tadr(hbuf, row, kl >> 3) + (kl & 7) * 2;
                asm volatile("st.shared.b32 [%0], %1;"
                             :: "r"(a), "r"(*reinterpret_cast<uint32_t*>(&p)) : "memory");
            }
        }
    }
    CPWAIT(0);
    __syncthreads();

    // -------- GEMM2: H[128x128] @ W1, 2 K=64 stages --------
    #pragma unroll
    for (int mi = 0; mi < 2; mi++)
        #pragma unroll
        for (int ni = 0; ni < 8; ni++)
            #pragma unroll
            for (int q = 0; q < 4; q++) acc[mi][ni][q] = 0.f;
    compute64(acc, BUF0, lane, wy, wx);
    compute64(acc, BUF1, lane, wy, wx);

    // -------- epilogue2: out = acc + s*b1 -> fp16 to global --------
    #pragma unroll
    for (int mi = 0; mi < 2; mi++) {
        #pragma unroll
        for (int ni = 0; ni < 8; ni++) {
            int ncol = wx * 64 + ni * 8 + (lane & 3) * 2;
            float bb0 = __ldg(&b1[ncol]) * SCALE;
            float bb1 = __ldg(&b1[ncol + 1]) * SCALE;
            #pragma unroll
            for (int h = 0; h < 2; h++) {
                int row = wy * 32 + mi * 16 + (lane >> 2) + h * 8;
                size_t gOff = (size_t)(blockIdx.x * 128 + row) * 128 + ncol;
                __half2 p = __floats2half2_rn(acc[mi][ni][2 * h] + bb0,
                                              acc[mi][ni][2 * h + 1] + bb1);
                *reinterpret_cast<uint32_t*>(fout + gOff) =
                    *reinterpret_cast<uint32_t*>(&p);
            }
        }
    }
}

// ---------------------------------------------------------------------------
// readout: logits[b] = dot(meanL, meanR)/s^2 + out_bias  (feats in g_f0)
// ---------------------------------------------------------------------------
__global__ void readout_k(const float* __restrict__ out_bias, float* __restrict__ logits) {
    const int b = blockIdx.x;
    const int t = threadIdx.x;   // 0..127
    size_t baseL = (size_t)(2 * b) * 64 * 128;
    size_t baseR = baseL + 64 * 128;
    float sl = 0.f, sr = 0.f;
    #pragma unroll 8
    for (int i = 0; i < 64; i++) {
        sl += __half2float(g_f0[baseL + i * 128 + t]);
        sr += __half2float(g_f0[baseR + i * 128 + t]);
    }
    float v = sl * sr;
    #pragma unroll
    for (int o = 16; o > 0; o >>= 1) v += __shfl_down_sync(0xffffffffu, v, o);
    __shared__ float red[4];
    if ((t & 31) == 0) red[t >> 5] = v;
    __syncthreads();
    if (t == 0)
        logits[b] = (red[0] + red[1] + red[2] + red[3]) *
                    (1.f / (4096.f * SCALE * SCALE)) + out_bias[0];
}

// ---------------------------------------------------------------------------
extern "C" void kernel_launch(void* const* d_in, const int* in_sizes, int n_in,
                              void* d_out, int out_size) {
    const int*   node_idx  = (const int*)  d_in[0];
    const int*   neighbors = (const int*)  d_in[1];
    const float* emb       = (const float*)d_in[3];
    const float* W0        = (const float*)d_in[4];
    const float* b0        = (const float*)d_in[5];
    const float* W1        = (const float*)d_in[6];
    const float* b1        = (const float*)d_in[7];
    const float* out_bias  = (const float*)d_in[8];
    float* logits = (float*)d_out;

    cudaFuncSetAttribute(layer_k, cudaFuncAttributeMaxDynamicSharedMemorySize, SMEM_BYTES);

    {
        int total = NUM_LAYERS * 10 * 2 * 8192;
        prep_w<<<(total + 255) / 256, 256>>>(W0, W1);
    }
    {
        int total = N_NODES * 32;
        embed_k<<<(total + 255) / 256, 256>>>(node_idx, emb);
    }
    for (int l = 0; l < NUM_LAYERS; l++) {
        layer_k<<<NUM_TILES, 256, SMEM_BYTES>>>(
            l, l & 1, neighbors,
            b0 + (size_t)l * 128,
            b1 + (size_t)l * 128);
    }
    readout_k<<<NUM_EQ, 128>>>(out_bias, logits);
}

// round 5
// speedup vs baseline: 8.8231x; 1.6076x over previous
#include <cuda_runtime.h>
#include <cuda_fp16.h>
#include <cstdint>

#define N_NODES   131072
#define NUM_LAYERS 4
#define NUM_EQ    1024
#define NUM_TILES 1024
#define SCALE 64.0f

// smem: [0..2048) neighbor ids, [4096 ..) 3 x 32KB stage bufs (A 16K | B 16K)
#define SMEM_BYTES (4096 + 3 * 32768)

// ---------------- static device buffers (no allocs allowed) ----------------
__device__ __align__(16) __half g_f0[N_NODES * 128];
__device__ __align__(16) __half g_f1[N_NODES * 128];
// weight blobs: [layer][sub 0..9][128 n-rows x 64 k fp16, ldsm-swizzled]
// sub 0..7 -> W0 K-chunks (K=512), sub 8..9 -> W1 K-chunks (K=128)
__device__ __align__(16) __half g_wblob[NUM_LAYERS * 10 * 8192];

// ---------------- helpers ----------------
__device__ __forceinline__ uint32_t smem_u32(const void* p) {
    uint32_t a;
    asm("{ .reg .u64 t; cvta.to.shared.u64 t, %1; cvt.u32.u64 %0, t; }"
        : "=r"(a) : "l"(p));
    return a;
}
#define CP16(dst, src, sz) \
    asm volatile("cp.async.cg.shared.global [%0], [%1], 16, %2;" \
                 :: "r"(dst), "l"(src), "r"(sz) : "memory")
#define CPCOMMIT() asm volatile("cp.async.commit_group;" ::: "memory")
#define CPWAIT0()  asm volatile("cp.async.wait_group 0;" ::: "memory")
#define CPWAIT1()  asm volatile("cp.async.wait_group 1;" ::: "memory")

__device__ __forceinline__ void ldsm4(uint32_t* r, uint32_t addr) {
    asm volatile("ldmatrix.sync.aligned.m8n8.x4.shared.b16 {%0,%1,%2,%3}, [%4];"
                 : "=r"(r[0]), "=r"(r[1]), "=r"(r[2]), "=r"(r[3]) : "r"(addr));
}
__device__ __forceinline__ void hmma(float* d, const uint32_t* a,
                                     uint32_t b0, uint32_t b1) {
    asm volatile(
        "mma.sync.aligned.m16n8k16.row.col.f32.f16.f16.f32 "
        "{%0,%1,%2,%3}, {%4,%5,%6,%7}, {%8,%9}, {%0,%1,%2,%3};"
        : "+f"(d[0]), "+f"(d[1]), "+f"(d[2]), "+f"(d[3])
        : "r"(a[0]), "r"(a[1]), "r"(a[2]), "r"(a[3]), "r"(b0), "r"(b1));
}
// tile: 128 rows x 64 k fp16 (128B rows, 8x16B chunks), XOR swizzle for ldsm
__device__ __forceinline__ uint32_t tadr(uint32_t base, int row, int ck) {
    return base + row * 128 + (((uint32_t)ck ^ (row & 7)) << 4);
}

// ---------------------------------------------------------------------------
// prep: transposed, ldsm-swizzled fp16 weight blobs
// ---------------------------------------------------------------------------
__global__ void prep_w(const float* __restrict__ W0, const float* __restrict__ W1) {
    int i = blockIdx.x * blockDim.x + threadIdx.x;
    if (i >= NUM_LAYERS * 10 * 8192) return;
    int e   = i & 8191;           // element within 8192-elem blob
    int g   = i >> 13;            // l*10 + sub
    int sub = g % 10;
    int l   = g / 10;
    int n   = e >> 6;             // N row 0..127
    int kk  = e & 63;             // K within subtile
    float w;
    if (sub < 8) w = W0[((size_t)l * 512 + sub * 64 + kk) * 128 + n];
    else         w = W1[((size_t)l * 128 + (sub - 8) * 64 + kk) * 128 + n];
    int ck = kk >> 3;
    uint32_t sw = (uint32_t)(n * 128) + (((uint32_t)ck ^ (n & 7)) << 4) + (kk & 7) * 2;
    *reinterpret_cast<__half*>(
        reinterpret_cast<char*>(g_wblob) + (size_t)(i - e) * 2 + sw) = __float2half_rn(w);
}

// ---------------------------------------------------------------------------
// embed: feats = SCALE * emb[node_idx]  -> fp16 into buffer 0
// ---------------------------------------------------------------------------
__global__ void embed_k(const int* __restrict__ node_idx, const float* __restrict__ emb) {
    int i = blockIdx.x * blockDim.x + threadIdx.x;   // one per 4 elems
    if (i >= N_NODES * 32) return;
    int n  = i >> 5;
    int c4 = i & 31;
    float4 vv = reinterpret_cast<const float4*>(emb)[node_idx[n] * 32 + c4];
    __half2 p0 = __floats2half2_rn(vv.x * SCALE, vv.y * SCALE);
    __half2 p1 = __floats2half2_rn(vv.z * SCALE, vv.w * SCALE);
    reinterpret_cast<uint2*>(g_f0)[i] =
        make_uint2(*reinterpret_cast<uint32_t*>(&p0), *reinterpret_cast<uint32_t*>(&p1));
}

// ---------------------------------------------------------------------------
// fused layer: plain fp16 HMMA, 3-stage cp.async ring
// ---------------------------------------------------------------------------
__device__ __forceinline__ void compute64(float acc[2][8][4], uint32_t buf,
                                          int lane, int wy, int wx) {
    #pragma unroll
    for (int ks = 0; ks < 4; ks++) {
        const int rsel = lane & 15;
        const int csel = 2 * ks + (lane >> 4);
        uint32_t a[2][4];
        #pragma unroll
        for (int mi = 0; mi < 2; mi++)
            ldsm4(a[mi], tadr(buf, wy * 32 + mi * 16 + rsel, csel));
        #pragma unroll
        for (int g = 0; g < 4; g++) {
            uint32_t b[4];
            ldsm4(b, tadr(buf + 16384, wx * 64 + g * 16 + rsel, csel));
            #pragma unroll
            for (int mi = 0; mi < 2; mi++) {
                hmma(acc[mi][2 * g],     a[mi], b[0], b[2]);
                hmma(acc[mi][2 * g + 1], a[mi], b[1], b[3]);
            }
        }
    }
}

__global__ __launch_bounds__(256, 2)
void layer_k(int l, int srcBuf, const int* __restrict__ neighbors,
             const float* __restrict__ b0, const float* __restrict__ b1) {
    extern __shared__ __align__(16) char smem[];
    int* sNbr = (int*)smem;
    const uint32_t sb = smem_u32(smem);
    const uint32_t BUF0 = sb + 4096, BUF1 = BUF0 + 32768, BUF2 = BUF0 + 65536;

    const int tid = threadIdx.x, lane = tid & 31, wid = tid >> 5;
    const int wy = wid >> 1, wx = wid & 1;

    const __half* fin = srcBuf ? g_f1 : g_f0;
    __half* fout      = srcBuf ? g_f0 : g_f1;

    sNbr[tid]       = neighbors[blockIdx.x * 512 + tid];
    sNbr[tid + 256] = neighbors[blockIdx.x * 512 + 256 + tid];
    __syncthreads();

    const char* finB  = reinterpret_cast<const char*>(fin);
    const char* blobB = reinterpret_cast<const char*>(g_wblob);

    // one K=64 stage: A gather (zfill for pad node) + B blob copy
    auto issue = [&](int s) {
        const uint32_t buf = BUF0 + (s % 3) * 32768;
        const int j = s >> 1, half = s & 1;
        const size_t blobOff = (size_t)(l * 10 + s) * 16384;
        #pragma unroll
        for (int r = 0; r < 4; r++) {
            int c = tid + 256 * r;                 // 0..1023
            int row = c >> 3, ck = c & 7;
            int sn = sNbr[row * 4 + j];
            uint32_t sz = (sn == N_NODES) ? 0u : 16u;
            size_t so = (size_t)sn * 256 + half * 128 + ck * 16;
            CP16(tadr(buf, row, ck), finB + so, sz);
            CP16(buf + 16384 + c * 16, blobB + blobOff + c * 16, 16u);
        }
    };

    float acc[2][8][4];
    #pragma unroll
    for (int mi = 0; mi < 2; mi++)
        #pragma unroll
        for (int ni = 0; ni < 8; ni++)
            #pragma unroll
            for (int q = 0; q < 4; q++) acc[mi][ni][q] = 0.f;

    // -------- GEMM1: gathered[128x512] @ W0, 8 K=64 stages, ring-3 --------
    issue(0); CPCOMMIT();
    issue(1); CPCOMMIT();
    #pragma unroll 1
    for (int s = 0; s < 8; s++) {
        if (s < 7) { CPWAIT1(); } else { CPWAIT0(); }
        __syncthreads();                 // group s visible to all warps;
                                         // also: all warps done with compute(s-1)
        if (s < 6) { issue(s + 2); CPCOMMIT(); }   // writes buf (s+2)%3 == (s-1)%3
        compute64(acc, BUF0 + (s % 3) * 32768, lane, wy, wx);
    }
    __syncthreads();                     // all warps done reading buf0/buf1

    // -------- epilogue1: W1 prefetch + H = relu(acc + s*b0) -> fp16 A tiles ----
    #pragma unroll
    for (int r = 0; r < 8; r++) {
        int idx = tid + 256 * r;                   // 0..2047
        int region = idx >> 10;                    // 0: W1 sub8 -> buf0.B, 1: sub9 -> buf1.B
        int c = idx & 1023;
        uint32_t dst = (region ? BUF1 : BUF0) + 16384 + c * 16;
        size_t src = (size_t)(l * 10 + 8 + region) * 16384 + (size_t)c * 16;
        CP16(dst, blobB + src, 16u);
    }
    CPCOMMIT();

    const uint32_t hbuf = wx ? BUF1 : BUF0;        // wx=0 -> k 0..63, wx=1 -> 64..127
    #pragma unroll
    for (int mi = 0; mi < 2; mi++) {
        #pragma unroll
        for (int ni = 0; ni < 8; ni++) {
            int kl = ni * 8 + (lane & 3) * 2;      // k within GEMM2 subtile
            int ncol = wx * 64 + kl;               // GEMM1 output column
            float bb0 = __ldg(&b0[ncol]) * SCALE;
            float bb1 = __ldg(&b0[ncol + 1]) * SCALE;
            #pragma unroll
            for (int h = 0; h < 2; h++) {          // row halves
                int row = wy * 32 + mi * 16 + (lane >> 2) + h * 8;
                float x0 = acc[mi][ni][2 * h]     + bb0;
                float x1 = acc[mi][ni][2 * h + 1] + bb1;
                x0 = x0 > 0.f ? x0 : 0.f;
                x1 = x1 > 0.f ? x1 : 0.f;
                __half2 p = __floats2half2_rn(x0, x1);
                uint32_t a = tadr(hbuf, row, kl >> 3) + (kl & 7) * 2;
                asm volatile("st.shared.b32 [%0], %1;"
                             :: "r"(a), "r"(*reinterpret_cast<uint32_t*>(&p)) : "memory");
            }
        }
    }
    CPWAIT0();
    __syncthreads();

    // -------- GEMM2: H[128x128] @ W1, 2 K=64 stages --------
    #pragma unroll
    for (int mi = 0; mi < 2; mi++)
        #pragma unroll
        for (int ni = 0; ni < 8; ni++)
            #pragma unroll
            for (int q = 0; q < 4; q++) acc[mi][ni][q] = 0.f;
    compute64(acc, BUF0, lane, wy, wx);
    compute64(acc, BUF1, lane, wy, wx);

    // -------- epilogue2: out = acc + s*b1 -> fp16 to global --------
    #pragma unroll
    for (int mi = 0; mi < 2; mi++) {
        #pragma unroll
        for (int ni = 0; ni < 8; ni++) {
            int ncol = wx * 64 + ni * 8 + (lane & 3) * 2;
            float bb0 = __ldg(&b1[ncol]) * SCALE;
            float bb1 = __ldg(&b1[ncol + 1]) * SCALE;
            #pragma unroll
            for (int h = 0; h < 2; h++) {
                int row = wy * 32 + mi * 16 + (lane >> 2) + h * 8;
                size_t gOff = (size_t)(blockIdx.x * 128 + row) * 128 + ncol;
                __half2 p = __floats2half2_rn(acc[mi][ni][2 * h] + bb0,
                                              acc[mi][ni][2 * h + 1] + bb1);
                *reinterpret_cast<uint32_t*>(fout + gOff) =
                    *reinterpret_cast<uint32_t*>(&p);
            }
        }
    }
}

// ---------------------------------------------------------------------------
// readout: logits[b] = dot(meanL, meanR)/s^2 + out_bias  (feats in g_f0)
// ---------------------------------------------------------------------------
__global__ void readout_k(const float* __restrict__ out_bias, float* __restrict__ logits) {
    const int b = blockIdx.x;
    const int t = threadIdx.x;   // 0..127
    size_t baseL = (size_t)(2 * b) * 64 * 128;
    size_t baseR = baseL + 64 * 128;
    float sl = 0.f, sr = 0.f;
    #pragma unroll 8
    for (int i = 0; i < 64; i++) {
        sl += __half2float(g_f0[baseL + i * 128 + t]);
        sr += __half2float(g_f0[baseR + i * 128 + t]);
    }
    float v = sl * sr;
    #pragma unroll
    for (int o = 16; o > 0; o >>= 1) v += __shfl_down_sync(0xffffffffu, v, o);
    __shared__ float red[4];
    if ((t & 31) == 0) red[t >> 5] = v;
    __syncthreads();
    if (t == 0)
        logits[b] = (red[0] + red[1] + red[2] + red[3]) *
                    (1.f / (4096.f * SCALE * SCALE)) + out_bias[0];
}

// ---------------------------------------------------------------------------
extern "C" void kernel_launch(void* const* d_in, const int* in_sizes, int n_in,
                              void* d_out, int out_size) {
    const int*   node_idx  = (const int*)  d_in[0];
    const int*   neighbors = (const int*)  d_in[1];
    const float* emb       = (const float*)d_in[3];
    const float* W0        = (const float*)d_in[4];
    const float* b0        = (const float*)d_in[5];
    const float* W1        = (const float*)d_in[6];
    const float* b1        = (const float*)d_in[7];
    const float* out_bias  = (const float*)d_in[8];
    float* logits = (float*)d_out;

    cudaFuncSetAttribute(layer_k, cudaFuncAttributeMaxDynamicSharedMemorySize, SMEM_BYTES);

    {
        int total = NUM_LAYERS * 10 * 8192;
        prep_w<<<(total + 255) / 256, 256>>>(W0, W1);
    }
    {
        int total = N_NODES * 32;
        embed_k<<<(total + 255) / 256, 256>>>(node_idx, emb);
    }
    for (int l = 0; l < NUM_LAYERS; l++) {
        layer_k<<<NUM_TILES, 256, SMEM_BYTES>>>(
            l, l & 1, neighbors,
            b0 + (size_t)l * 128,
            b1 + (size_t)l * 128);
    }
    readout_k<<<NUM_EQ, 128>>>(out_bias, logits);
}